// round 16
// baseline (speedup 1.0000x reference)
#include <cuda_runtime.h>
#include <cuda_fp16.h>
#include <math.h>
#include <stdint.h>

// ---------------------------------------------------------------- constants
#define BB    64
#define SS    128
#define EMB_  512
#define ENC2_ 1024
#define ATTN_ 512
#define DECH_ 1024
#define VOCAB_ 32000
#define XKC   2560
#define OUTK  2560
#define G4    (4 * DECH_)

#define OFF_OUT 0
#define OFF_NH  (BB * VOCAB_)
#define OFF_NC  (OFF_NH + BB * DECH_)
#define OFF_AW  (OFF_NC + BB * DECH_)
#define OUT_TOTAL (OFF_AW + BB * SS)

// scratch (no device allocations allowed)
__device__ __align__(16) float g_decp[BB * ATTN_];
__device__ __align__(16) float g_scores[BB * SS];
__device__ __align__(16) float g_xbuf[BB * XKC];   // [emb|ctx|hidden]
__device__ __align__(16) float g_obuf[BB * OUTK];  // [nh|ctx|emb]
__device__ __align__(16) float g_gates[BB * G4];
__device__ __align__(16) __half g_wenc_h[ATTN_ * ENC2_];       // 1 MB
__device__ __align__(16) __half g_enc_h[(size_t)SS * BB * ENC2_]; // 16.8 MB
__device__ __align__(16) float g_aux[BB * DECH_ * 2 + BB * SS];

// ---------------------------------------------------------------- helpers
#define MMA16816(c, a, b) \
    asm volatile("mma.sync.aligned.m16n8k16.row.col.f32.f16.f16.f32 " \
        "{%0,%1,%2,%3},{%4,%5,%6,%7},{%8,%9},{%0,%1,%2,%3};" \
        : "+f"(c[0]), "+f"(c[1]), "+f"(c[2]), "+f"(c[3]) \
        : "r"(a[0]), "r"(a[1]), "r"(a[2]), "r"(a[3]), "r"(b[0]), "r"(b[1]))

#define LDSM4(d0, d1, d2, d3, addr) \
    asm volatile("ldmatrix.sync.aligned.m8n8.x4.shared.b16 {%0,%1,%2,%3}, [%4];" \
        : "=r"(d0), "=r"(d1), "=r"(d2), "=r"(d3) : "r"(addr))

__device__ __forceinline__ uint32_t smem_u32(const void* p) {
    uint32_t a;
    asm("{ .reg .u64 t; cvta.to.shared.u64 t, %1; cvt.u32.u64 %0, t; }" : "=r"(a) : "l"(p));
    return a;
}

__device__ __forceinline__ void split4(float4 v, uint2& h, uint2& l)
{
    __half2 h01 = __floats2half2_rn(v.x, v.y);
    __half2 h23 = __floats2half2_rn(v.z, v.w);
    float2 f01 = __half22float2(h01);
    float2 f23 = __half22float2(h23);
    __half2 l01 = __floats2half2_rn(v.x - f01.x, v.y - f01.y);
    __half2 l23 = __floats2half2_rn(v.z - f23.x, v.w - f23.y);
    h.x = *(uint32_t*)&h01; h.y = *(uint32_t*)&h23;
    l.x = *(uint32_t*)&l01; l.y = *(uint32_t*)&l23;
}
__device__ __forceinline__ void hi4(float4 v, uint2& h)
{
    __half2 h01 = __floats2half2_rn(v.x, v.y);
    __half2 h23 = __floats2half2_rn(v.z, v.w);
    h.x = *(uint32_t*)&h01; h.y = *(uint32_t*)&h23;
}

// ================================================================ fp32->fp16 converters
__global__ void __launch_bounds__(256)
cvt_wenc_k(const float* __restrict__ W)
{
    const int i = (blockIdx.x * 256 + threadIdx.x) * 4;
    float4 v = *(const float4*)(W + i);
    uint2 h;
    hi4(v, h);
    *(uint2*)&g_wenc_h[i] = h;
}

// enc_out: 8.4M elems, 8 per thread
__global__ void __launch_bounds__(256)
cvt_enc_k(const float* __restrict__ E)
{
    const size_t i = ((size_t)blockIdx.x * 256 + threadIdx.x) * 8;
    float4 v0 = *(const float4*)(E + i);
    float4 v1 = *(const float4*)(E + i + 4);
    uint2 h0, h1;
    hi4(v0, h0);
    hi4(v1, h1);
    uint4 packed = make_uint4(h0.x, h0.y, h1.x, h1.y);
    *(uint4*)&g_enc_h[i] = packed;
}

// ================================================================ generic GEMM
// (dec_proj / gates) — BM=64, BN=128, BK=32, 256 thr.
#define BKK 32
#define LDK 40
#define STAGE_A  0
#define STAGE_AL 2560
#define STAGE_B  5120
#define STAGE_BL 10240
#define STAGE_SZ 15360
#define SMEM_BYTES (2 * STAGE_SZ * 2)  // 61440

template<int EPI, int ATOM, int NPROD>
__global__ void __launch_bounds__(256, 2)
gemm_k(const float* __restrict__ A, int lda,
       const float* __restrict__ B1, int ldb1, int ksplit,
       const float* __restrict__ B2, int ldb2,
       float* __restrict__ C, int N, int kslice,
       const float* __restrict__ bias,
       const float* __restrict__ decp,
       const float* __restrict__ vat)
{
    extern __shared__ __half sm[];
    const uint32_t sb0 = smem_u32(sm);

    const int tid = threadIdx.x;
    const int wid = tid >> 5, lane = tid & 31;
    const int g = lane >> 2, tig = lane & 3;
    const int wm = wid >> 2, wn = wid & 3;
    const int bm = blockIdx.y * 64, bn = blockIdx.x * 128;
    const int k0 = blockIdx.z * kslice;
    const int nk = kslice / BKK;

    const int lrow = tid >> 3;
    const int lkq  = tid & 7;
    const int rowsel = lane & 15;
    const int kcsel  = (lane >> 4) * 8;

    float4 pa0, pa1, pb[4];

    {
        const int gk = k0 + lkq * 4;
        pa0 = *(const float4*)(A + (size_t)(bm + lrow) * lda + gk);
        pa1 = *(const float4*)(A + (size_t)(bm + lrow + 32) * lda + gk);
        #pragma unroll
        for (int r = 0; r < 4; r++) {
            const int n = bn + lrow + r * 32;
            const float* Bp = (gk < ksplit)
                ? (B1 + (size_t)n * ldb1 + gk)
                : (B2 + (size_t)n * ldb2 + (gk - ksplit));
            pb[r] = *(const float4*)Bp;
        }
    }
    {
        __half* st = sm;
        uint2 h, l;
        if (NPROD >= 2) {
            split4(pa0, h, l);
            *(uint2*)&st[STAGE_A  + lrow * LDK + lkq * 4] = h;
            *(uint2*)&st[STAGE_AL + lrow * LDK + lkq * 4] = l;
            split4(pa1, h, l);
            *(uint2*)&st[STAGE_A  + (lrow + 32) * LDK + lkq * 4] = h;
            *(uint2*)&st[STAGE_AL + (lrow + 32) * LDK + lkq * 4] = l;
        } else {
            hi4(pa0, h);
            *(uint2*)&st[STAGE_A  + lrow * LDK + lkq * 4] = h;
            hi4(pa1, h);
            *(uint2*)&st[STAGE_A  + (lrow + 32) * LDK + lkq * 4] = h;
        }
        #pragma unroll
        for (int r = 0; r < 4; r++) {
            if (NPROD == 3) {
                split4(pb[r], h, l);
                *(uint2*)&st[STAGE_B  + (lrow + r * 32) * LDK + lkq * 4] = h;
                *(uint2*)&st[STAGE_BL + (lrow + r * 32) * LDK + lkq * 4] = l;
            } else {
                hi4(pb[r], h);
                *(uint2*)&st[STAGE_B  + (lrow + r * 32) * LDK + lkq * 4] = h;
            }
        }
    }
    __syncthreads();

    float acc[2][4][4];
    #pragma unroll
    for (int mt = 0; mt < 2; mt++)
        #pragma unroll
        for (int nt = 0; nt < 4; nt++)
            #pragma unroll
            for (int q = 0; q < 4; q++) acc[mt][nt][q] = 0.f;

    for (int kt = 0; kt < nk; kt++) {
        const uint32_t cu = sb0 + (uint32_t)(kt & 1) * (STAGE_SZ * 2);
        __half* nxt = sm + ((kt + 1) & 1) * STAGE_SZ;

        if (kt + 1 < nk) {
            const int gk = k0 + (kt + 1) * BKK + lkq * 4;
            pa0 = *(const float4*)(A + (size_t)(bm + lrow) * lda + gk);
            pa1 = *(const float4*)(A + (size_t)(bm + lrow + 32) * lda + gk);
            #pragma unroll
            for (int r = 0; r < 4; r++) {
                const int n = bn + lrow + r * 32;
                const float* Bp = (gk < ksplit)
                    ? (B1 + (size_t)n * ldb1 + gk)
                    : (B2 + (size_t)n * ldb2 + (gk - ksplit));
                pb[r] = *(const float4*)Bp;
            }
        }

        #pragma unroll
        for (int ks = 0; ks < 2; ks++) {
            const int ks16 = ks * 16;
            uint32_t ah[2][4], al[2][4], bh[4][2], bl[4][2];
            #pragma unroll
            for (int mt = 0; mt < 2; mt++) {
                const int r = wm * 32 + mt * 16;
                const uint32_t a_addr =
                    cu + 2u * (STAGE_A + (r + rowsel) * LDK + ks16 + kcsel);
                LDSM4(ah[mt][0], ah[mt][1], ah[mt][2], ah[mt][3], a_addr);
                if (NPROD >= 2) {
                    const uint32_t al_addr =
                        cu + 2u * (STAGE_AL + (r + rowsel) * LDK + ks16 + kcsel);
                    LDSM4(al[mt][0], al[mt][1], al[mt][2], al[mt][3], al_addr);
                }
            }
            {
                const uint32_t b_addr =
                    cu + 2u * (STAGE_B + (wn * 32 + lane) * LDK + ks16);
                LDSM4(bh[0][0], bh[1][0], bh[2][0], bh[3][0], b_addr);
                LDSM4(bh[0][1], bh[1][1], bh[2][1], bh[3][1], b_addr + 16);
                if (NPROD == 3) {
                    const uint32_t bl_addr =
                        cu + 2u * (STAGE_BL + (wn * 32 + lane) * LDK + ks16);
                    LDSM4(bl[0][0], bl[1][0], bl[2][0], bl[3][0], bl_addr);
                    LDSM4(bl[0][1], bl[1][1], bl[2][1], bl[3][1], bl_addr + 16);
                }
            }
            #pragma unroll
            for (int mt = 0; mt < 2; mt++)
                #pragma unroll
                for (int nt = 0; nt < 4; nt++) {
                    MMA16816(acc[mt][nt], ah[mt], bh[nt]);
                    if (NPROD == 3) MMA16816(acc[mt][nt], ah[mt], bl[nt]);
                    if (NPROD >= 2) MMA16816(acc[mt][nt], al[mt], bh[nt]);
                }
        }

        if (kt + 1 < nk) {
            uint2 h, l;
            if (NPROD >= 2) {
                split4(pa0, h, l);
                *(uint2*)&nxt[STAGE_A  + lrow * LDK + lkq * 4] = h;
                *(uint2*)&nxt[STAGE_AL + lrow * LDK + lkq * 4] = l;
                split4(pa1, h, l);
                *(uint2*)&nxt[STAGE_A  + (lrow + 32) * LDK + lkq * 4] = h;
                *(uint2*)&nxt[STAGE_AL + (lrow + 32) * LDK + lkq * 4] = l;
            } else {
                hi4(pa0, h);
                *(uint2*)&nxt[STAGE_A  + lrow * LDK + lkq * 4] = h;
                hi4(pa1, h);
                *(uint2*)&nxt[STAGE_A  + (lrow + 32) * LDK + lkq * 4] = h;
            }
            #pragma unroll
            for (int r = 0; r < 4; r++) {
                if (NPROD == 3) {
                    split4(pb[r], h, l);
                    *(uint2*)&nxt[STAGE_B  + (lrow + r * 32) * LDK + lkq * 4] = h;
                    *(uint2*)&nxt[STAGE_BL + (lrow + r * 32) * LDK + lkq * 4] = l;
                } else {
                    hi4(pb[r], h);
                    *(uint2*)&nxt[STAGE_B  + (lrow + r * 32) * LDK + lkq * 4] = h;
                }
            }
        }
        __syncthreads();
    }

    #pragma unroll
    for (int mt = 0; mt < 2; mt++) {
        const int gm = bm + wm * 32 + mt * 16 + g;
        #pragma unroll
        for (int nt = 0; nt < 4; nt++) {
            const int gn = bn + wn * 32 + nt * 8 + tig * 2;
            if (ATOM) {
                atomicAdd(C + (size_t)gm * N + gn,       acc[mt][nt][0]);
                atomicAdd(C + (size_t)gm * N + gn + 1,   acc[mt][nt][1]);
                atomicAdd(C + (size_t)(gm + 8) * N + gn,     acc[mt][nt][2]);
                atomicAdd(C + (size_t)(gm + 8) * N + gn + 1, acc[mt][nt][3]);
            } else {
                const float b0 = bias ? bias[gn] : 0.f;
                const float b1 = bias ? bias[gn + 1] : 0.f;
                *(float2*)(C + (size_t)gm * N + gn) =
                    make_float2(acc[mt][nt][0] + b0, acc[mt][nt][1] + b1);
                *(float2*)(C + (size_t)(gm + 8) * N + gn) =
                    make_float2(acc[mt][nt][2] + b0, acc[mt][nt][3] + b1);
            }
        }
    }
}

// ================================================================ out GEMM
// M=64 (fixed), BN=128, BK=32, nk=80, 1-product fp16, 2-deep register prefetch.
#define OSTG_A 0
#define OSTG_B 2560
#define OSTG_SZ 7680
#define OSMEM_BYTES (2 * OSTG_SZ * 2)   // 30720

#define OUT_LDG(it, s) do { \
    const int gk = (it) * BKK + lkq * 4; \
    a0[s] = *(const float4*)(A + (size_t)lrow * OUTK + gk); \
    a1[s] = *(const float4*)(A + (size_t)(lrow + 32) * OUTK + gk); \
    b4[s][0] = *(const float4*)(Bm + (size_t)(bn + lrow)      * OUTK + gk); \
    b4[s][1] = *(const float4*)(Bm + (size_t)(bn + lrow + 32) * OUTK + gk); \
    b4[s][2] = *(const float4*)(Bm + (size_t)(bn + lrow + 64) * OUTK + gk); \
    b4[s][3] = *(const float4*)(Bm + (size_t)(bn + lrow + 96) * OUTK + gk); \
} while (0)

#define OUT_STS(s, stg) do { \
    __half* st = sm + (stg) * OSTG_SZ; \
    uint2 h; \
    hi4(a0[s], h); *(uint2*)&st[OSTG_A + lrow * LDK + lkq * 4] = h; \
    hi4(a1[s], h); *(uint2*)&st[OSTG_A + (lrow + 32) * LDK + lkq * 4] = h; \
    hi4(b4[s][0], h); *(uint2*)&st[OSTG_B + lrow * LDK + lkq * 4] = h; \
    hi4(b4[s][1], h); *(uint2*)&st[OSTG_B + (lrow + 32) * LDK + lkq * 4] = h; \
    hi4(b4[s][2], h); *(uint2*)&st[OSTG_B + (lrow + 64) * LDK + lkq * 4] = h; \
    hi4(b4[s][3], h); *(uint2*)&st[OSTG_B + (lrow + 96) * LDK + lkq * 4] = h; \
} while (0)

#define OUT_MMA(stg) do { \
    const uint32_t cu = sb0 + (uint32_t)(stg) * (OSTG_SZ * 2); \
    _Pragma("unroll") \
    for (int ks = 0; ks < 2; ks++) { \
        const int ks16 = ks * 16; \
        uint32_t ah[2][4], bh[4][2]; \
        _Pragma("unroll") \
        for (int mt = 0; mt < 2; mt++) { \
            const int r = wm * 32 + mt * 16; \
            const uint32_t a_addr = \
                cu + 2u * (OSTG_A + (r + rowsel) * LDK + ks16 + kcsel); \
            LDSM4(ah[mt][0], ah[mt][1], ah[mt][2], ah[mt][3], a_addr); \
        } \
        { \
            const uint32_t b_addr = \
                cu + 2u * (OSTG_B + (wn * 32 + lane) * LDK + ks16); \
            LDSM4(bh[0][0], bh[1][0], bh[2][0], bh[3][0], b_addr); \
            LDSM4(bh[0][1], bh[1][1], bh[2][1], bh[3][1], b_addr + 16); \
        } \
        _Pragma("unroll") \
        for (int mt = 0; mt < 2; mt++) \
            _Pragma("unroll") \
            for (int nt = 0; nt < 4; nt++) \
                MMA16816(acc[mt][nt], ah[mt], bh[nt]); \
    } \
} while (0)

__global__ void __launch_bounds__(256, 2)
gemm_out_k(const float* __restrict__ A,      // obuf [64, 2560]
           const float* __restrict__ Bm,     // W_out [32000, 2560]
           float* __restrict__ C,            // out [64, 32000]
           const float* __restrict__ bias)
{
    extern __shared__ __half sm[];
    const uint32_t sb0 = smem_u32(sm);

    const int tid = threadIdx.x;
    const int wid = tid >> 5, lane = tid & 31;
    const int g = lane >> 2, tig = lane & 3;
    const int wm = wid >> 2, wn = wid & 3;
    const int bn = blockIdx.x * 128;
    const int nk = OUTK / BKK;   // 80

    const int lrow = tid >> 3, lkq = tid & 7;
    const int rowsel = lane & 15, kcsel = (lane >> 4) * 8;

    float4 a0[2], a1[2], b4[2][4];

    OUT_LDG(0, 0);
    OUT_STS(0, 0);
    OUT_LDG(1, 1);
    OUT_LDG(2, 0);
    __syncthreads();

    float acc[2][4][4];
    #pragma unroll
    for (int mt = 0; mt < 2; mt++)
        #pragma unroll
        for (int nt = 0; nt < 4; nt++)
            #pragma unroll
            for (int q = 0; q < 4; q++) acc[mt][nt][q] = 0.f;

    for (int kt = 0; kt < nk; kt += 2) {
        OUT_MMA(0);
        OUT_STS(1, 1);
        if (kt + 3 < nk) OUT_LDG(kt + 3, 1);
        __syncthreads();

        OUT_MMA(1);
        if (kt + 2 < nk) {
            OUT_STS(0, 0);
            if (kt + 4 < nk) OUT_LDG(kt + 4, 0);
        }
        __syncthreads();
    }

    #pragma unroll
    for (int mt = 0; mt < 2; mt++) {
        const int gm = wm * 32 + mt * 16 + g;
        #pragma unroll
        for (int nt = 0; nt < 4; nt++) {
            const int gn = bn + wn * 32 + nt * 8 + tig * 2;
            const float b0 = bias[gn];
            const float b1 = bias[gn + 1];
            *(float2*)(C + (size_t)gm * VOCAB_ + gn) =
                make_float2(acc[mt][nt][0] + b0, acc[mt][nt][1] + b1);
            *(float2*)(C + (size_t)(gm + 8) * VOCAB_ + gn) =
                make_float2(acc[mt][nt][2] + b0, acc[mt][nt][3] + b1);
        }
    }
}

// ================================================================ enc GEMM
// BM=128, BN=256, BK=32, 512 threads. Both operands pre-converted fp16:
// loader is a pure uint4 copy (no converts, half the LDG sectors of R13).
#define ESTG_A 0
#define ESTG_B 5120
#define ESTG_SZ 15360
#define ESMEM_BYTES (2 * ESTG_SZ * 2)

__global__ void __launch_bounds__(512, 1)
gemm_enc_k(const __half* __restrict__ Ah16,    // enc_out fp16 [8192, 1024]
           const __half* __restrict__ Bh16,    // W_enc fp16 [512, 1024]
           const float* __restrict__ decp,
           const float* __restrict__ vat)
{
    extern __shared__ __half sm[];
    const uint32_t sb0 = smem_u32(sm);

    const int tid = threadIdx.x;
    const int wid = tid >> 5, lane = tid & 31;
    const int g = lane >> 2, tig = lane & 3;
    const int wm = wid >> 2, wn = wid & 3;
    const int bm = blockIdx.y * 128, bn = blockIdx.x * 256;

    // uint4 copy mapping: 4 threads per 32-half row segment
    const int lrowA = tid >> 2;          // 0..127
    const int lkqA  = (tid & 3) * 8;     // 0,8,16,24 (halfs)
    const int rowsel = lane & 15;
    const int kcsel  = (lane >> 4) * 8;

    const int nk = ENC2_ / BKK;  // 32

    uint4 pa, pb[2];

    {
        const int gk = lkqA;
        pa = *(const uint4*)(Ah16 + (size_t)(bm + lrowA) * ENC2_ + gk);
        #pragma unroll
        for (int r = 0; r < 2; r++)
            pb[r] = *(const uint4*)(Bh16 + (size_t)(bn + lrowA + r * 128) * ENC2_ + gk);
    }
    {
        __half* st = sm;
        *(uint4*)&st[ESTG_A + lrowA * LDK + lkqA] = pa;
        #pragma unroll
        for (int r = 0; r < 2; r++)
            *(uint4*)&st[ESTG_B + (lrowA + r * 128) * LDK + lkqA] = pb[r];
    }
    __syncthreads();

    float acc[2][8][4];
    #pragma unroll
    for (int mt = 0; mt < 2; mt++)
        #pragma unroll
        for (int nt = 0; nt < 8; nt++)
            #pragma unroll
            for (int q = 0; q < 4; q++) acc[mt][nt][q] = 0.f;

    for (int kt = 0; kt < nk; kt++) {
        const uint32_t cu = sb0 + (uint32_t)(kt & 1) * (ESTG_SZ * 2);
        __half* nxt = sm + ((kt + 1) & 1) * ESTG_SZ;

        if (kt + 1 < nk) {
            const int gk = (kt + 1) * BKK + lkqA;
            pa = *(const uint4*)(Ah16 + (size_t)(bm + lrowA) * ENC2_ + gk);
            #pragma unroll
            for (int r = 0; r < 2; r++)
                pb[r] = *(const uint4*)(Bh16 + (size_t)(bn + lrowA + r * 128) * ENC2_ + gk);
        }

        #pragma unroll
        for (int ks = 0; ks < 2; ks++) {
            const int ks16 = ks * 16;
            uint32_t ah[2][4], bh[8][2];
            #pragma unroll
            for (int mt = 0; mt < 2; mt++) {
                const int r = wm * 32 + mt * 16;
                const uint32_t a_addr =
                    cu + 2u * (ESTG_A + (r + rowsel) * LDK + ks16 + kcsel);
                LDSM4(ah[mt][0], ah[mt][1], ah[mt][2], ah[mt][3], a_addr);
            }
            {
                const uint32_t b1a =
                    cu + 2u * (ESTG_B + (wn * 64 + lane) * LDK + ks16);
                LDSM4(bh[0][0], bh[1][0], bh[2][0], bh[3][0], b1a);
                LDSM4(bh[0][1], bh[1][1], bh[2][1], bh[3][1], b1a + 16);
                const uint32_t b2a =
                    cu + 2u * (ESTG_B + (wn * 64 + 32 + lane) * LDK + ks16);
                LDSM4(bh[4][0], bh[5][0], bh[6][0], bh[7][0], b2a);
                LDSM4(bh[4][1], bh[5][1], bh[6][1], bh[7][1], b2a + 16);
            }
            #pragma unroll
            for (int mt = 0; mt < 2; mt++)
                #pragma unroll
                for (int nt = 0; nt < 8; nt++)
                    MMA16816(acc[mt][nt], ah[mt], bh[nt]);
        }

        if (kt + 1 < nk) {
            *(uint4*)&nxt[ESTG_A + lrowA * LDK + lkqA] = pa;
            #pragma unroll
            for (int r = 0; r < 2; r++)
                *(uint4*)&nxt[ESTG_B + (lrowA + r * 128) * LDK + lkqA] = pb[r];
        }
        __syncthreads();
    }

    // score epilogue: row gm -> (b = gm&63, s = gm>>6); c2/c3 are row gm+8
    #pragma unroll
    for (int mt = 0; mt < 2; mt++) {
        const int gm = bm + wm * 32 + mt * 16 + g;
        const int bA = gm & 63;
        const int bBt = (gm + 8) & 63;
        float p0 = 0.f, p8 = 0.f;
        #pragma unroll
        for (int nt = 0; nt < 8; nt++) {
            const int gn = bn + wn * 64 + nt * 8 + tig * 2;
            const float d0a = decp[bA * ATTN_ + gn],  d1a = decp[bA * ATTN_ + gn + 1];
            const float d0b = decp[bBt * ATTN_ + gn], d1b = decp[bBt * ATTN_ + gn + 1];
            const float v0 = vat[gn], v1 = vat[gn + 1];
            p0 += tanhf(acc[mt][nt][0] + d0a) * v0 + tanhf(acc[mt][nt][1] + d1a) * v1;
            p8 += tanhf(acc[mt][nt][2] + d0b) * v0 + tanhf(acc[mt][nt][3] + d1b) * v1;
        }
        p0 += __shfl_xor_sync(0xffffffffu, p0, 1);
        p0 += __shfl_xor_sync(0xffffffffu, p0, 2);
        p8 += __shfl_xor_sync(0xffffffffu, p8, 1);
        p8 += __shfl_xor_sync(0xffffffffu, p8, 2);
        if (tig == 0) {
            atomicAdd(&g_scores[bA * SS + (gm >> 6)], p0);
            atomicAdd(&g_scores[bBt * SS + ((gm + 8) >> 6)], p8);
        }
    }
}

// ---------------------------------------------------------------- embed etc.
__global__ void __launch_bounds__(256)
embed_copy_k(const int* __restrict__ tok, const float* __restrict__ emb,
             const float* __restrict__ hidden)
{
    int b = blockIdx.x, tid = threadIdx.x;
    int t = tok[b];
    const float* src = emb + (size_t)t * EMB_;
    for (int j = tid; j < EMB_; j += 256) {
        float v = (t == 0) ? 0.f : src[j];
        g_xbuf[b * XKC + j] = v;
        g_obuf[b * OUTK + (DECH_ + ENC2_) + j] = v;
        g_decp[b * ATTN_ + j] = 0.f;
    }
    for (int j = tid; j < DECH_; j += 256) {
        g_xbuf[b * XKC + (EMB_ + ENC2_) + j] = hidden[b * DECH_ + j];
        g_xbuf[b * XKC + EMB_ + j] = 0.f;
    }
    for (int j = tid; j < G4; j += 256)
        g_gates[b * G4 + j] = 0.f;
    if (tid < SS) g_scores[b * SS + tid] = 0.f;
}

// softmax + partial context; grid (16, 64): x = half*8 + schunk; 128 threads.
__global__ void __launch_bounds__(128)
smctx_k(const int* __restrict__ mask, const float* __restrict__ enc_out,
        float* __restrict__ aw_dst)
{
    int b = blockIdx.y, half = blockIdx.x >> 3, sc = blockIdx.x & 7;
    int tid = threadIdx.x;
    int wid = tid >> 5, lane = tid & 31;
    __shared__ float w[SS];
    __shared__ float red[4];

    float val = (mask[b * SS + tid] == 0) ? -INFINITY : g_scores[b * SS + tid];
    float m = val;
    #pragma unroll
    for (int o = 16; o; o >>= 1) m = fmaxf(m, __shfl_xor_sync(0xffffffffu, m, o));
    if (lane == 0) red[wid] = m;
    __syncthreads();
    if (tid == 0) red[0] = fmaxf(fmaxf(red[0], red[1]), fmaxf(red[2], red[3]));
    __syncthreads();
    float mx = red[0];
    __syncthreads();

    float e = __expf(val - mx);
    float ssum = e;
    #pragma unroll
    for (int o = 16; o; o >>= 1) ssum += __shfl_xor_sync(0xffffffffu, ssum, o);
    if (lane == 0) red[wid] = ssum;
    __syncthreads();
    if (tid == 0) red[0] = red[0] + red[1] + red[2] + red[3];
    __syncthreads();
    float ww = e / red[0];
    w[tid] = ww;
    if (blockIdx.x == 0) aw_dst[b * SS + tid] = ww;
    __syncthreads();

    const int col = half * 512 + tid * 4;
    const float* base = enc_out + (size_t)b * ENC2_ + col;
    float4 a = make_float4(0.f, 0.f, 0.f, 0.f);
    const int s0 = sc * 16;
    #pragma unroll 8
    for (int s = s0; s < s0 + 16; s++) {
        float ws = w[s];
        float4 v = *(const float4*)(base + (size_t)s * BB * ENC2_);
        a.x = fmaf(ws, v.x, a.x); a.y = fmaf(ws, v.y, a.y);
        a.z = fmaf(ws, v.z, a.z); a.w = fmaf(ws, v.w, a.w);
    }
    float* dst = &g_xbuf[b * XKC + EMB_ + col];
    atomicAdd(dst + 0, a.x);
    atomicAdd(dst + 1, a.y);
    atomicAdd(dst + 2, a.z);
    atomicAdd(dst + 3, a.w);
}

// LSTM pointwise; also copies ctx g_xbuf -> g_obuf
__global__ void __launch_bounds__(1024)
lstm_k(const float* __restrict__ b_ih, const float* __restrict__ b_hh,
       const float* __restrict__ cell,
       float* __restrict__ nh_out, float* __restrict__ nc_out)
{
    int b = blockIdx.x, j = threadIdx.x;
    const float* gg = g_gates + (size_t)b * G4;
    float iv = gg[j]             + b_ih[j]             + b_hh[j];
    float fv = gg[j + DECH_]     + b_ih[j + DECH_]     + b_hh[j + DECH_];
    float gv = gg[j + 2 * DECH_] + b_ih[j + 2 * DECH_] + b_hh[j + 2 * DECH_];
    float ov = gg[j + 3 * DECH_] + b_ih[j + 3 * DECH_] + b_hh[j + 3 * DECH_];
    float i_ = 1.f / (1.f + __expf(-iv));
    float f_ = 1.f / (1.f + __expf(-fv));
    float o_ = 1.f / (1.f + __expf(-ov));
    float gt = tanhf(gv);
    float nc = f_ * cell[b * DECH_ + j] + i_ * gt;
    float nh = o_ * tanhf(nc);
    nc_out[b * DECH_ + j] = nc;
    nh_out[b * DECH_ + j] = nh;
    g_obuf[b * OUTK + j] = nh;
    g_obuf[b * OUTK + DECH_ + j] = g_xbuf[b * XKC + EMB_ + j];
}

// ---------------------------------------------------------------- launcher
extern "C" void kernel_launch(void* const* d_in, const int* in_sizes, int n_in,
                              void* d_out, int out_size)
{
    const int*   input_token = (const int*)  d_in[0];
    const float* hidden      = (const float*)d_in[1];
    const float* cell        = (const float*)d_in[2];
    const float* enc_out     = (const float*)d_in[3];
    const int*   mask        = (const int*)  d_in[4];
    const float* embedding   = (const float*)d_in[5];
    const float* W_enc       = (const float*)d_in[6];
    const float* W_dec       = (const float*)d_in[7];
    const float* v_attn      = (const float*)d_in[8];
    const float* W_ih        = (const float*)d_in[9];
    const float* W_hh        = (const float*)d_in[10];
    const float* b_ih        = (const float*)d_in[11];
    const float* b_hh        = (const float*)d_in[12];
    const float* W_out       = (const float*)d_in[13];
    const float* b_out       = (const float*)d_in[14];

    float* out = (float*)d_out;

    void *p_decp, *p_xbuf, *p_obuf, *p_gates, *p_wench, *p_ench, *p_aux;
    cudaGetSymbolAddress(&p_decp,  g_decp);
    cudaGetSymbolAddress(&p_xbuf,  g_xbuf);
    cudaGetSymbolAddress(&p_obuf,  g_obuf);
    cudaGetSymbolAddress(&p_gates, g_gates);
    cudaGetSymbolAddress(&p_wench, g_wenc_h);
    cudaGetSymbolAddress(&p_ench,  g_enc_h);
    cudaGetSymbolAddress(&p_aux,   g_aux);

    cudaFuncSetAttribute(gemm_k<0,1,2>, cudaFuncAttributeMaxDynamicSharedMemorySize, SMEM_BYTES);
    cudaFuncSetAttribute(gemm_enc_k, cudaFuncAttributeMaxDynamicSharedMemorySize, ESMEM_BYTES);
    cudaFuncSetAttribute(gemm_out_k, cudaFuncAttributeMaxDynamicSharedMemorySize, OSMEM_BYTES);

    bool full = (out_size >= OUT_TOTAL);
    float* nh_dst = full ? out + OFF_NH : (float*)p_aux;
    float* nc_dst = full ? out + OFF_NC : (float*)p_aux + BB * DECH_;
    float* aw_dst = full ? out + OFF_AW : (float*)p_aux + 2 * BB * DECH_;

    // side stream: convert enc_out fp32->fp16 overlapped with wenc/embed/dec
    cudaStream_t s2;
    cudaStreamCreateWithFlags(&s2, cudaStreamNonBlocking);
    cudaEvent_t evF, evC;
    cudaEventCreateWithFlags(&evF, cudaEventDisableTiming);
    cudaEventCreateWithFlags(&evC, cudaEventDisableTiming);

    cudaEventRecord(evF, 0);
    cudaStreamWaitEvent(s2, evF, 0);
    cvt_enc_k<<<(int)(((size_t)SS * BB * ENC2_) / 2048), 256, 0, s2>>>(enc_out);
    cudaEventRecord(evC, s2);

    // 0) W_enc fp32 -> fp16
    cvt_wenc_k<<<(ATTN_ * ENC2_) / 1024, 256>>>(W_enc);

    // 1) embedding + hidden copy + zero accumulators
    embed_copy_k<<<BB, 256>>>(input_token, embedding, hidden);

    // 2) dec_proj (split-K x8, atomic, 2-product)
    gemm_k<0,1,2><<<dim3(ATTN_ / 128, 1, 8), 256, SMEM_BYTES>>>(
        hidden, DECH_, W_dec, DECH_, DECH_, W_dec, DECH_,
        (float*)p_decp, ATTN_, DECH_ / 8, nullptr, nullptr, nullptr);

    // join: fp16 enc_out ready
    cudaStreamWaitEvent(0, evC, 0);

    // 3) enc_proj GEMM + fused score reduction (both operands fp16)
    gemm_enc_k<<<dim3(ATTN_ / 256, (SS * BB) / 128), 512, ESMEM_BYTES>>>(
        (const __half*)p_ench, (const __half*)p_wench, (const float*)p_decp, v_attn);

    // 4) softmax + context (fp32 enc_out — numerics unchanged)
    smctx_k<<<dim3(16, BB), 128>>>(mask, enc_out, aw_dst);

    // 5) gates (split-K x4, 2-product)
    gemm_k<0,1,2><<<dim3(G4 / 128, 1, 4), 256, SMEM_BYTES>>>(
        (const float*)p_xbuf, XKC, W_ih, EMB_ + ENC2_, EMB_ + ENC2_, W_hh, DECH_,
        (float*)p_gates, G4, XKC / 4, nullptr, nullptr, nullptr);

    // 6) LSTM pointwise + ctx copy
    lstm_k<<<BB, DECH_>>>(b_ih, b_hh, cell, nh_dst, nc_dst);

    // 7) output = [nh|ctx|emb] @ W_out^T + b_out (1-product, 2-deep prefetch)
    gemm_out_k<<<dim3(VOCAB_ / 128), 256, OSMEM_BYTES>>>(
        (const float*)p_obuf, W_out, out + OFF_OUT, b_out);
}

// round 17
// speedup vs baseline: 1.0978x; 1.0978x over previous
#include <cuda_runtime.h>
#include <cuda_fp16.h>
#include <math.h>
#include <stdint.h>

// ---------------------------------------------------------------- constants
#define BB    64
#define SS    128
#define EMB_  512
#define ENC2_ 1024
#define ATTN_ 512
#define DECH_ 1024
#define VOCAB_ 32000
#define XKC   2560
#define OUTK  2560
#define G4    (4 * DECH_)

#define OFF_OUT 0
#define OFF_NH  (BB * VOCAB_)
#define OFF_NC  (OFF_NH + BB * DECH_)
#define OFF_AW  (OFF_NC + BB * DECH_)
#define OUT_TOTAL (OFF_AW + BB * SS)

// scratch (no allocations allowed)
__device__ __align__(16) float g_decp[BB * ATTN_];
__device__ __align__(16) float g_scores[BB * SS];
__device__ __align__(16) float g_xbuf[BB * XKC];   // [emb|ctx|hidden]
__device__ __align__(16) float g_obuf[BB * OUTK];  // [nh|ctx|emb]
__device__ __align__(16) float g_gates[BB * G4];
__device__ __align__(16) __half g_wenc_h[ATTN_ * ENC2_];  // fp16 W_enc (1 MB)
__device__ __align__(16) float g_aux[BB * DECH_ * 2 + BB * SS];

// ---------------------------------------------------------------- helpers
#define MMA16816(c, a, b) \
    asm volatile("mma.sync.aligned.m16n8k16.row.col.f32.f16.f16.f32 " \
        "{%0,%1,%2,%3},{%4,%5,%6,%7},{%8,%9},{%0,%1,%2,%3};" \
        : "+f"(c[0]), "+f"(c[1]), "+f"(c[2]), "+f"(c[3]) \
        : "r"(a[0]), "r"(a[1]), "r"(a[2]), "r"(a[3]), "r"(b[0]), "r"(b[1]))

#define LDSM4(d0, d1, d2, d3, addr) \
    asm volatile("ldmatrix.sync.aligned.m8n8.x4.shared.b16 {%0,%1,%2,%3}, [%4];" \
        : "=r"(d0), "=r"(d1), "=r"(d2), "=r"(d3) : "r"(addr))

__device__ __forceinline__ uint32_t smem_u32(const void* p) {
    uint32_t a;
    asm("{ .reg .u64 t; cvta.to.shared.u64 t, %1; cvt.u32.u64 %0, t; }" : "=r"(a) : "l"(p));
    return a;
}

__device__ __forceinline__ void split4(float4 v, uint2& h, uint2& l)
{
    __half2 h01 = __floats2half2_rn(v.x, v.y);
    __half2 h23 = __floats2half2_rn(v.z, v.w);
    float2 f01 = __half22float2(h01);
    float2 f23 = __half22float2(h23);
    __half2 l01 = __floats2half2_rn(v.x - f01.x, v.y - f01.y);
    __half2 l23 = __floats2half2_rn(v.z - f23.x, v.w - f23.y);
    h.x = *(uint32_t*)&h01; h.y = *(uint32_t*)&h23;
    l.x = *(uint32_t*)&l01; l.y = *(uint32_t*)&l23;
}
__device__ __forceinline__ void hi4(float4 v, uint2& h)
{
    __half2 h01 = __floats2half2_rn(v.x, v.y);
    __half2 h23 = __floats2half2_rn(v.z, v.w);
    h.x = *(uint32_t*)&h01; h.y = *(uint32_t*)&h23;
}

// ================================================================ W_enc fp32->fp16
__global__ void __launch_bounds__(256)
cvt_wenc_k(const float* __restrict__ W)
{
    const int i = (blockIdx.x * 256 + threadIdx.x) * 4;
    float4 v = *(const float4*)(W + i);
    uint2 h;
    hi4(v, h);
    *(uint2*)&g_wenc_h[i] = h;
}

// ================================================================ generic GEMM
// (dec_proj / gates) — BM=64, BN=128, BK=32, 256 thr.
#define BKK 32
#define LDK 40
#define STAGE_A  0
#define STAGE_AL 2560
#define STAGE_B  5120
#define STAGE_BL 10240
#define STAGE_SZ 15360
#define SMEM_BYTES (2 * STAGE_SZ * 2)  // 61440

template<int EPI, int ATOM, int NPROD>
__global__ void __launch_bounds__(256, 2)
gemm_k(const float* __restrict__ A, int lda,
       const float* __restrict__ B1, int ldb1, int ksplit,
       const float* __restrict__ B2, int ldb2,
       float* __restrict__ C, int N, int kslice,
       const float* __restrict__ bias,
       const float* __restrict__ decp,
       const float* __restrict__ vat)
{
    extern __shared__ __half sm[];
    const uint32_t sb0 = smem_u32(sm);

    const int tid = threadIdx.x;
    const int wid = tid >> 5, lane = tid & 31;
    const int g = lane >> 2, tig = lane & 3;
    const int wm = wid >> 2, wn = wid & 3;
    const int bm = blockIdx.y * 64, bn = blockIdx.x * 128;
    const int k0 = blockIdx.z * kslice;
    const int nk = kslice / BKK;

    const int lrow = tid >> 3;
    const int lkq  = tid & 7;
    const int rowsel = lane & 15;
    const int kcsel  = (lane >> 4) * 8;

    float4 pa0, pa1, pb[4];

    {
        const int gk = k0 + lkq * 4;
        pa0 = *(const float4*)(A + (size_t)(bm + lrow) * lda + gk);
        pa1 = *(const float4*)(A + (size_t)(bm + lrow + 32) * lda + gk);
        #pragma unroll
        for (int r = 0; r < 4; r++) {
            const int n = bn + lrow + r * 32;
            const float* Bp = (gk < ksplit)
                ? (B1 + (size_t)n * ldb1 + gk)
                : (B2 + (size_t)n * ldb2 + (gk - ksplit));
            pb[r] = *(const float4*)Bp;
        }
    }
    {
        __half* st = sm;
        uint2 h, l;
        if (NPROD >= 2) {
            split4(pa0, h, l);
            *(uint2*)&st[STAGE_A  + lrow * LDK + lkq * 4] = h;
            *(uint2*)&st[STAGE_AL + lrow * LDK + lkq * 4] = l;
            split4(pa1, h, l);
            *(uint2*)&st[STAGE_A  + (lrow + 32) * LDK + lkq * 4] = h;
            *(uint2*)&st[STAGE_AL + (lrow + 32) * LDK + lkq * 4] = l;
        } else {
            hi4(pa0, h);
            *(uint2*)&st[STAGE_A  + lrow * LDK + lkq * 4] = h;
            hi4(pa1, h);
            *(uint2*)&st[STAGE_A  + (lrow + 32) * LDK + lkq * 4] = h;
        }
        #pragma unroll
        for (int r = 0; r < 4; r++) {
            if (NPROD == 3) {
                split4(pb[r], h, l);
                *(uint2*)&st[STAGE_B  + (lrow + r * 32) * LDK + lkq * 4] = h;
                *(uint2*)&st[STAGE_BL + (lrow + r * 32) * LDK + lkq * 4] = l;
            } else {
                hi4(pb[r], h);
                *(uint2*)&st[STAGE_B  + (lrow + r * 32) * LDK + lkq * 4] = h;
            }
        }
    }
    __syncthreads();

    float acc[2][4][4];
    #pragma unroll
    for (int mt = 0; mt < 2; mt++)
        #pragma unroll
        for (int nt = 0; nt < 4; nt++)
            #pragma unroll
            for (int q = 0; q < 4; q++) acc[mt][nt][q] = 0.f;

    for (int kt = 0; kt < nk; kt++) {
        const uint32_t cu = sb0 + (uint32_t)(kt & 1) * (STAGE_SZ * 2);
        __half* nxt = sm + ((kt + 1) & 1) * STAGE_SZ;

        if (kt + 1 < nk) {
            const int gk = k0 + (kt + 1) * BKK + lkq * 4;
            pa0 = *(const float4*)(A + (size_t)(bm + lrow) * lda + gk);
            pa1 = *(const float4*)(A + (size_t)(bm + lrow + 32) * lda + gk);
            #pragma unroll
            for (int r = 0; r < 4; r++) {
                const int n = bn + lrow + r * 32;
                const float* Bp = (gk < ksplit)
                    ? (B1 + (size_t)n * ldb1 + gk)
                    : (B2 + (size_t)n * ldb2 + (gk - ksplit));
                pb[r] = *(const float4*)Bp;
            }
        }

        #pragma unroll
        for (int ks = 0; ks < 2; ks++) {
            const int ks16 = ks * 16;
            uint32_t ah[2][4], al[2][4], bh[4][2], bl[4][2];
            #pragma unroll
            for (int mt = 0; mt < 2; mt++) {
                const int r = wm * 32 + mt * 16;
                const uint32_t a_addr =
                    cu + 2u * (STAGE_A + (r + rowsel) * LDK + ks16 + kcsel);
                LDSM4(ah[mt][0], ah[mt][1], ah[mt][2], ah[mt][3], a_addr);
                if (NPROD >= 2) {
                    const uint32_t al_addr =
                        cu + 2u * (STAGE_AL + (r + rowsel) * LDK + ks16 + kcsel);
                    LDSM4(al[mt][0], al[mt][1], al[mt][2], al[mt][3], al_addr);
                }
            }
            {
                const uint32_t b_addr =
                    cu + 2u * (STAGE_B + (wn * 32 + lane) * LDK + ks16);
                LDSM4(bh[0][0], bh[1][0], bh[2][0], bh[3][0], b_addr);
                LDSM4(bh[0][1], bh[1][1], bh[2][1], bh[3][1], b_addr + 16);
                if (NPROD == 3) {
                    const uint32_t bl_addr =
                        cu + 2u * (STAGE_BL + (wn * 32 + lane) * LDK + ks16);
                    LDSM4(bl[0][0], bl[1][0], bl[2][0], bl[3][0], bl_addr);
                    LDSM4(bl[0][1], bl[1][1], bl[2][1], bl[3][1], bl_addr + 16);
                }
            }
            #pragma unroll
            for (int mt = 0; mt < 2; mt++)
                #pragma unroll
                for (int nt = 0; nt < 4; nt++) {
                    MMA16816(acc[mt][nt], ah[mt], bh[nt]);
                    if (NPROD == 3) MMA16816(acc[mt][nt], ah[mt], bl[nt]);
                    if (NPROD >= 2) MMA16816(acc[mt][nt], al[mt], bh[nt]);
                }
        }

        if (kt + 1 < nk) {
            uint2 h, l;
            if (NPROD >= 2) {
                split4(pa0, h, l);
                *(uint2*)&nxt[STAGE_A  + lrow * LDK + lkq * 4] = h;
                *(uint2*)&nxt[STAGE_AL + lrow * LDK + lkq * 4] = l;
                split4(pa1, h, l);
                *(uint2*)&nxt[STAGE_A  + (lrow + 32) * LDK + lkq * 4] = h;
                *(uint2*)&nxt[STAGE_AL + (lrow + 32) * LDK + lkq * 4] = l;
            } else {
                hi4(pa0, h);
                *(uint2*)&nxt[STAGE_A  + lrow * LDK + lkq * 4] = h;
                hi4(pa1, h);
                *(uint2*)&nxt[STAGE_A  + (lrow + 32) * LDK + lkq * 4] = h;
            }
            #pragma unroll
            for (int r = 0; r < 4; r++) {
                if (NPROD == 3) {
                    split4(pb[r], h, l);
                    *(uint2*)&nxt[STAGE_B  + (lrow + r * 32) * LDK + lkq * 4] = h;
                    *(uint2*)&nxt[STAGE_BL + (lrow + r * 32) * LDK + lkq * 4] = l;
                } else {
                    hi4(pb[r], h);
                    *(uint2*)&nxt[STAGE_B  + (lrow + r * 32) * LDK + lkq * 4] = h;
                }
            }
        }
        __syncthreads();
    }

    #pragma unroll
    for (int mt = 0; mt < 2; mt++) {
        const int gm = bm + wm * 32 + mt * 16 + g;
        #pragma unroll
        for (int nt = 0; nt < 4; nt++) {
            const int gn = bn + wn * 32 + nt * 8 + tig * 2;
            if (ATOM) {
                atomicAdd(C + (size_t)gm * N + gn,       acc[mt][nt][0]);
                atomicAdd(C + (size_t)gm * N + gn + 1,   acc[mt][nt][1]);
                atomicAdd(C + (size_t)(gm + 8) * N + gn,     acc[mt][nt][2]);
                atomicAdd(C + (size_t)(gm + 8) * N + gn + 1, acc[mt][nt][3]);
            } else {
                const float b0 = bias ? bias[gn] : 0.f;
                const float b1 = bias ? bias[gn + 1] : 0.f;
                *(float2*)(C + (size_t)gm * N + gn) =
                    make_float2(acc[mt][nt][0] + b0, acc[mt][nt][1] + b1);
                *(float2*)(C + (size_t)(gm + 8) * N + gn) =
                    make_float2(acc[mt][nt][2] + b0, acc[mt][nt][3] + b1);
            }
        }
    }
}

// ================================================================ out GEMM
// M=64 (fixed), BN=128, BK=32, nk=80, 1-product fp16, 2-deep register prefetch.
#define OSTG_A 0
#define OSTG_B 2560
#define OSTG_SZ 7680
#define OSMEM_BYTES (2 * OSTG_SZ * 2)   // 30720

#define OUT_LDG(it, s) do { \
    const int gk = (it) * BKK + lkq * 4; \
    a0[s] = *(const float4*)(A + (size_t)lrow * OUTK + gk); \
    a1[s] = *(const float4*)(A + (size_t)(lrow + 32) * OUTK + gk); \
    b4[s][0] = *(const float4*)(Bm + (size_t)(bn + lrow)      * OUTK + gk); \
    b4[s][1] = *(const float4*)(Bm + (size_t)(bn + lrow + 32) * OUTK + gk); \
    b4[s][2] = *(const float4*)(Bm + (size_t)(bn + lrow + 64) * OUTK + gk); \
    b4[s][3] = *(const float4*)(Bm + (size_t)(bn + lrow + 96) * OUTK + gk); \
} while (0)

#define OUT_STS(s, stg) do { \
    __half* st = sm + (stg) * OSTG_SZ; \
    uint2 h; \
    hi4(a0[s], h); *(uint2*)&st[OSTG_A + lrow * LDK + lkq * 4] = h; \
    hi4(a1[s], h); *(uint2*)&st[OSTG_A + (lrow + 32) * LDK + lkq * 4] = h; \
    hi4(b4[s][0], h); *(uint2*)&st[OSTG_B + lrow * LDK + lkq * 4] = h; \
    hi4(b4[s][1], h); *(uint2*)&st[OSTG_B + (lrow + 32) * LDK + lkq * 4] = h; \
    hi4(b4[s][2], h); *(uint2*)&st[OSTG_B + (lrow + 64) * LDK + lkq * 4] = h; \
    hi4(b4[s][3], h); *(uint2*)&st[OSTG_B + (lrow + 96) * LDK + lkq * 4] = h; \
} while (0)

#define OUT_MMA(stg) do { \
    const uint32_t cu = sb0 + (uint32_t)(stg) * (OSTG_SZ * 2); \
    _Pragma("unroll") \
    for (int ks = 0; ks < 2; ks++) { \
        const int ks16 = ks * 16; \
        uint32_t ah[2][4], bh[4][2]; \
        _Pragma("unroll") \
        for (int mt = 0; mt < 2; mt++) { \
            const int r = wm * 32 + mt * 16; \
            const uint32_t a_addr = \
                cu + 2u * (OSTG_A + (r + rowsel) * LDK + ks16 + kcsel); \
            LDSM4(ah[mt][0], ah[mt][1], ah[mt][2], ah[mt][3], a_addr); \
        } \
        { \
            const uint32_t b_addr = \
                cu + 2u * (OSTG_B + (wn * 32 + lane) * LDK + ks16); \
            LDSM4(bh[0][0], bh[1][0], bh[2][0], bh[3][0], b_addr); \
            LDSM4(bh[0][1], bh[1][1], bh[2][1], bh[3][1], b_addr + 16); \
        } \
        _Pragma("unroll") \
        for (int mt = 0; mt < 2; mt++) \
            _Pragma("unroll") \
            for (int nt = 0; nt < 4; nt++) \
                MMA16816(acc[mt][nt], ah[mt], bh[nt]); \
    } \
} while (0)

__global__ void __launch_bounds__(256, 2)
gemm_out_k(const float* __restrict__ A,      // obuf [64, 2560]
           const float* __restrict__ Bm,     // W_out [32000, 2560]
           float* __restrict__ C,            // out [64, 32000]
           const float* __restrict__ bias)
{
    extern __shared__ __half sm[];
    const uint32_t sb0 = smem_u32(sm);

    const int tid = threadIdx.x;
    const int wid = tid >> 5, lane = tid & 31;
    const int g = lane >> 2, tig = lane & 3;
    const int wm = wid >> 2, wn = wid & 3;
    const int bn = blockIdx.x * 128;
    const int nk = OUTK / BKK;   // 80

    const int lrow = tid >> 3, lkq = tid & 7;
    const int rowsel = lane & 15, kcsel = (lane >> 4) * 8;

    float4 a0[2], a1[2], b4[2][4];

    OUT_LDG(0, 0);
    OUT_STS(0, 0);
    OUT_LDG(1, 1);
    OUT_LDG(2, 0);
    __syncthreads();

    float acc[2][4][4];
    #pragma unroll
    for (int mt = 0; mt < 2; mt++)
        #pragma unroll
        for (int nt = 0; nt < 4; nt++)
            #pragma unroll
            for (int q = 0; q < 4; q++) acc[mt][nt][q] = 0.f;

    for (int kt = 0; kt < nk; kt += 2) {
        OUT_MMA(0);
        OUT_STS(1, 1);
        if (kt + 3 < nk) OUT_LDG(kt + 3, 1);
        __syncthreads();

        OUT_MMA(1);
        if (kt + 2 < nk) {
            OUT_STS(0, 0);
            if (kt + 4 < nk) OUT_LDG(kt + 4, 0);
        }
        __syncthreads();
    }

    #pragma unroll
    for (int mt = 0; mt < 2; mt++) {
        const int gm = wm * 32 + mt * 16 + g;
        #pragma unroll
        for (int nt = 0; nt < 4; nt++) {
            const int gn = bn + wn * 32 + nt * 8 + tig * 2;
            const float b0 = bias[gn];
            const float b1 = bias[gn + 1];
            *(float2*)(C + (size_t)gm * VOCAB_ + gn) =
                make_float2(acc[mt][nt][0] + b0, acc[mt][nt][1] + b1);
            *(float2*)(C + (size_t)(gm + 8) * VOCAB_ + gn) =
                make_float2(acc[mt][nt][2] + b0, acc[mt][nt][3] + b1);
        }
    }
}

// ================================================================ enc GEMM (R13 config)
// BM=128, BN=256, BK=32, 512 threads. B = pre-converted fp16 W_enc.
#define ESTG_A 0
#define ESTG_B 5120
#define ESTG_SZ 15360
#define ESMEM_BYTES (2 * ESTG_SZ * 2)

__global__ void __launch_bounds__(512, 1)
gemm_enc_k(const float* __restrict__ A,        // enc_out [8192, 1024] fp32
           const __half* __restrict__ Bh16,    // W_enc fp16 [512, 1024]
           const float* __restrict__ decp,
           const float* __restrict__ vat)
{
    extern __shared__ __half sm[];
    const uint32_t sb0 = smem_u32(sm);

    const int tid = threadIdx.x;
    const int wid = tid >> 5, lane = tid & 31;
    const int g = lane >> 2, tig = lane & 3;
    const int wm = wid >> 2, wn = wid & 3;
    const int bm = blockIdx.y * 128, bn = blockIdx.x * 256;

    const int lrow = tid >> 3;   // 0..63
    const int lkq  = tid & 7;
    const int rowsel = lane & 15;
    const int kcsel  = (lane >> 4) * 8;

    const int nk = ENC2_ / BKK;  // 32

    float4 pa0, pa1;
    uint2 pbh[4];

    {
        const int gk = lkq * 4;
        pa0 = *(const float4*)(A + (size_t)(bm + lrow) * ENC2_ + gk);
        pa1 = *(const float4*)(A + (size_t)(bm + lrow + 64) * ENC2_ + gk);
        #pragma unroll
        for (int r = 0; r < 4; r++)
            pbh[r] = *(const uint2*)(Bh16 + (size_t)(bn + lrow + r * 64) * ENC2_ + gk);
    }
    {
        __half* st = sm;
        uint2 h;
        hi4(pa0, h); *(uint2*)&st[ESTG_A + lrow * LDK + lkq * 4] = h;
        hi4(pa1, h); *(uint2*)&st[ESTG_A + (lrow + 64) * LDK + lkq * 4] = h;
        #pragma unroll
        for (int r = 0; r < 4; r++)
            *(uint2*)&st[ESTG_B + (lrow + r * 64) * LDK + lkq * 4] = pbh[r];
    }
    __syncthreads();

    float acc[2][8][4];
    #pragma unroll
    for (int mt = 0; mt < 2; mt++)
        #pragma unroll
        for (int nt = 0; nt < 8; nt++)
            #pragma unroll
            for (int q = 0; q < 4; q++) acc[mt][nt][q] = 0.f;

    for (int kt = 0; kt < nk; kt++) {
        const uint32_t cu = sb0 + (uint32_t)(kt & 1) * (ESTG_SZ * 2);
        __half* nxt = sm + ((kt + 1) & 1) * ESTG_SZ;

        if (kt + 1 < nk) {
            const int gk = (kt + 1) * BKK + lkq * 4;
            pa0 = *(const float4*)(A + (size_t)(bm + lrow) * ENC2_ + gk);
            pa1 = *(const float4*)(A + (size_t)(bm + lrow + 64) * ENC2_ + gk);
            #pragma unroll
            for (int r = 0; r < 4; r++)
                pbh[r] = *(const uint2*)(Bh16 + (size_t)(bn + lrow + r * 64) * ENC2_ + gk);
        }

        #pragma unroll
        for (int ks = 0; ks < 2; ks++) {
            const int ks16 = ks * 16;
            uint32_t ah[2][4], bh[8][2];
            #pragma unroll
            for (int mt = 0; mt < 2; mt++) {
                const int r = wm * 32 + mt * 16;
                const uint32_t a_addr =
                    cu + 2u * (ESTG_A + (r + rowsel) * LDK + ks16 + kcsel);
                LDSM4(ah[mt][0], ah[mt][1], ah[mt][2], ah[mt][3], a_addr);
            }
            {
                const uint32_t b1a =
                    cu + 2u * (ESTG_B + (wn * 64 + lane) * LDK + ks16);
                LDSM4(bh[0][0], bh[1][0], bh[2][0], bh[3][0], b1a);
                LDSM4(bh[0][1], bh[1][1], bh[2][1], bh[3][1], b1a + 16);
                const uint32_t b2a =
                    cu + 2u * (ESTG_B + (wn * 64 + 32 + lane) * LDK + ks16);
                LDSM4(bh[4][0], bh[5][0], bh[6][0], bh[7][0], b2a);
                LDSM4(bh[4][1], bh[5][1], bh[6][1], bh[7][1], b2a + 16);
            }
            #pragma unroll
            for (int mt = 0; mt < 2; mt++)
                #pragma unroll
                for (int nt = 0; nt < 8; nt++)
                    MMA16816(acc[mt][nt], ah[mt], bh[nt]);
        }

        if (kt + 1 < nk) {
            uint2 h;
            hi4(pa0, h); *(uint2*)&nxt[ESTG_A + lrow * LDK + lkq * 4] = h;
            hi4(pa1, h); *(uint2*)&nxt[ESTG_A + (lrow + 64) * LDK + lkq * 4] = h;
            #pragma unroll
            for (int r = 0; r < 4; r++)
                *(uint2*)&nxt[ESTG_B + (lrow + r * 64) * LDK + lkq * 4] = pbh[r];
        }
        __syncthreads();
    }

    // score epilogue: row gm -> (b = gm&63, s = gm>>6); c2/c3 are row gm+8
    #pragma unroll
    for (int mt = 0; mt < 2; mt++) {
        const int gm = bm + wm * 32 + mt * 16 + g;
        const int bA = gm & 63;
        const int bBt = (gm + 8) & 63;
        float p0 = 0.f, p8 = 0.f;
        #pragma unroll
        for (int nt = 0; nt < 8; nt++) {
            const int gn = bn + wn * 64 + nt * 8 + tig * 2;
            const float d0a = decp[bA * ATTN_ + gn],  d1a = decp[bA * ATTN_ + gn + 1];
            const float d0b = decp[bBt * ATTN_ + gn], d1b = decp[bBt * ATTN_ + gn + 1];
            const float v0 = vat[gn], v1 = vat[gn + 1];
            p0 += tanhf(acc[mt][nt][0] + d0a) * v0 + tanhf(acc[mt][nt][1] + d1a) * v1;
            p8 += tanhf(acc[mt][nt][2] + d0b) * v0 + tanhf(acc[mt][nt][3] + d1b) * v1;
        }
        p0 += __shfl_xor_sync(0xffffffffu, p0, 1);
        p0 += __shfl_xor_sync(0xffffffffu, p0, 2);
        p8 += __shfl_xor_sync(0xffffffffu, p8, 1);
        p8 += __shfl_xor_sync(0xffffffffu, p8, 2);
        if (tig == 0) {
            atomicAdd(&g_scores[bA * SS + (gm >> 6)], p0);
            atomicAdd(&g_scores[bBt * SS + ((gm + 8) >> 6)], p8);
        }
    }
}

// ---------------------------------------------------------------- embed etc.
__global__ void __launch_bounds__(256)
embed_copy_k(const int* __restrict__ tok, const float* __restrict__ emb,
             const float* __restrict__ hidden)
{
    int b = blockIdx.x, tid = threadIdx.x;
    int t = tok[b];
    const float* src = emb + (size_t)t * EMB_;
    for (int j = tid; j < EMB_; j += 256) {
        float v = (t == 0) ? 0.f : src[j];
        g_xbuf[b * XKC + j] = v;
        g_obuf[b * OUTK + (DECH_ + ENC2_) + j] = v;
        g_decp[b * ATTN_ + j] = 0.f;
    }
    for (int j = tid; j < DECH_; j += 256) {
        g_xbuf[b * XKC + (EMB_ + ENC2_) + j] = hidden[b * DECH_ + j];
        g_xbuf[b * XKC + EMB_ + j] = 0.f;
    }
    for (int j = tid; j < G4; j += 256)
        g_gates[b * G4 + j] = 0.f;
    if (tid < SS) g_scores[b * SS + tid] = 0.f;
}

// softmax + partial context; grid (16, 64): x = half*8 + schunk; 128 threads.
__global__ void __launch_bounds__(128)
smctx_k(const int* __restrict__ mask, const float* __restrict__ enc_out,
        float* __restrict__ aw_dst)
{
    int b = blockIdx.y, half = blockIdx.x >> 3, sc = blockIdx.x & 7;
    int tid = threadIdx.x;
    int wid = tid >> 5, lane = tid & 31;
    __shared__ float w[SS];
    __shared__ float red[4];

    float val = (mask[b * SS + tid] == 0) ? -INFINITY : g_scores[b * SS + tid];
    float m = val;
    #pragma unroll
    for (int o = 16; o; o >>= 1) m = fmaxf(m, __shfl_xor_sync(0xffffffffu, m, o));
    if (lane == 0) red[wid] = m;
    __syncthreads();
    if (tid == 0) red[0] = fmaxf(fmaxf(red[0], red[1]), fmaxf(red[2], red[3]));
    __syncthreads();
    float mx = red[0];
    __syncthreads();

    float e = __expf(val - mx);
    float ssum = e;
    #pragma unroll
    for (int o = 16; o; o >>= 1) ssum += __shfl_xor_sync(0xffffffffu, ssum, o);
    if (lane == 0) red[wid] = ssum;
    __syncthreads();
    if (tid == 0) red[0] = red[0] + red[1] + red[2] + red[3];
    __syncthreads();
    float ww = e / red[0];
    w[tid] = ww;
    if (blockIdx.x == 0) aw_dst[b * SS + tid] = ww;
    __syncthreads();

    const int col = half * 512 + tid * 4;
    const float* base = enc_out + (size_t)b * ENC2_ + col;
    float4 a = make_float4(0.f, 0.f, 0.f, 0.f);
    const int s0 = sc * 16;
    #pragma unroll 8
    for (int s = s0; s < s0 + 16; s++) {
        float ws = w[s];
        float4 v = *(const float4*)(base + (size_t)s * BB * ENC2_);
        a.x = fmaf(ws, v.x, a.x); a.y = fmaf(ws, v.y, a.y);
        a.z = fmaf(ws, v.z, a.z); a.w = fmaf(ws, v.w, a.w);
    }
    float* dst = &g_xbuf[b * XKC + EMB_ + col];
    atomicAdd(dst + 0, a.x);
    atomicAdd(dst + 1, a.y);
    atomicAdd(dst + 2, a.z);
    atomicAdd(dst + 3, a.w);
}

// LSTM pointwise; also copies ctx g_xbuf -> g_obuf
__global__ void __launch_bounds__(1024)
lstm_k(const float* __restrict__ b_ih, const float* __restrict__ b_hh,
       const float* __restrict__ cell,
       float* __restrict__ nh_out, float* __restrict__ nc_out)
{
    int b = blockIdx.x, j = threadIdx.x;
    const float* gg = g_gates + (size_t)b * G4;
    float iv = gg[j]             + b_ih[j]             + b_hh[j];
    float fv = gg[j + DECH_]     + b_ih[j + DECH_]     + b_hh[j + DECH_];
    float gv = gg[j + 2 * DECH_] + b_ih[j + 2 * DECH_] + b_hh[j + 2 * DECH_];
    float ov = gg[j + 3 * DECH_] + b_ih[j + 3 * DECH_] + b_hh[j + 3 * DECH_];
    float i_ = 1.f / (1.f + __expf(-iv));
    float f_ = 1.f / (1.f + __expf(-fv));
    float o_ = 1.f / (1.f + __expf(-ov));
    float gt = tanhf(gv);
    float nc = f_ * cell[b * DECH_ + j] + i_ * gt;
    float nh = o_ * tanhf(nc);
    nc_out[b * DECH_ + j] = nc;
    nh_out[b * DECH_ + j] = nh;
    g_obuf[b * OUTK + j] = nh;
    g_obuf[b * OUTK + DECH_ + j] = g_xbuf[b * XKC + EMB_ + j];
}

// ---------------------------------------------------------------- launcher
extern "C" void kernel_launch(void* const* d_in, const int* in_sizes, int n_in,
                              void* d_out, int out_size)
{
    const int*   input_token = (const int*)  d_in[0];
    const float* hidden      = (const float*)d_in[1];
    const float* cell        = (const float*)d_in[2];
    const float* enc_out     = (const float*)d_in[3];
    const int*   mask        = (const int*)  d_in[4];
    const float* embedding   = (const float*)d_in[5];
    const float* W_enc       = (const float*)d_in[6];
    const float* W_dec       = (const float*)d_in[7];
    const float* v_attn      = (const float*)d_in[8];
    const float* W_ih        = (const float*)d_in[9];
    const float* W_hh        = (const float*)d_in[10];
    const float* b_ih        = (const float*)d_in[11];
    const float* b_hh        = (const float*)d_in[12];
    const float* W_out       = (const float*)d_in[13];
    const float* b_out       = (const float*)d_in[14];

    float* out = (float*)d_out;

    void *p_decp, *p_xbuf, *p_obuf, *p_gates, *p_wench, *p_aux;
    cudaGetSymbolAddress(&p_decp,  g_decp);
    cudaGetSymbolAddress(&p_xbuf,  g_xbuf);
    cudaGetSymbolAddress(&p_obuf,  g_obuf);
    cudaGetSymbolAddress(&p_gates, g_gates);
    cudaGetSymbolAddress(&p_wench, g_wenc_h);
    cudaGetSymbolAddress(&p_aux,   g_aux);

    cudaFuncSetAttribute(gemm_k<0,1,2>, cudaFuncAttributeMaxDynamicSharedMemorySize, SMEM_BYTES);
    cudaFuncSetAttribute(gemm_enc_k, cudaFuncAttributeMaxDynamicSharedMemorySize, ESMEM_BYTES);
    cudaFuncSetAttribute(gemm_out_k, cudaFuncAttributeMaxDynamicSharedMemorySize, OSMEM_BYTES);

    bool full = (out_size >= OUT_TOTAL);
    float* nh_dst = full ? out + OFF_NH : (float*)p_aux;
    float* nc_dst = full ? out + OFF_NC : (float*)p_aux + BB * DECH_;
    float* aw_dst = full ? out + OFF_AW : (float*)p_aux + 2 * BB * DECH_;

    // 0) W_enc fp32 -> fp16 (bit-identical to in-GEMM truncation)
    cvt_wenc_k<<<(ATTN_ * ENC2_) / 1024, 256>>>(W_enc);

    // 1) embedding + hidden copy + zero scores/ctx/decp/gates
    embed_copy_k<<<BB, 256>>>(input_token, embedding, hidden);

    // 2) dec_proj[64,512] = hidden @ W_dec^T (split-K x16, atomic, 2-product)
    gemm_k<0,1,2><<<dim3(ATTN_ / 128, 1, 16), 256, SMEM_BYTES>>>(
        hidden, DECH_, W_dec, DECH_, DECH_, W_dec, DECH_,
        (float*)p_decp, ATTN_, DECH_ / 16, nullptr, nullptr, nullptr);

    // 3) enc_proj GEMM + fused score reduction (big-tile, fp16 B)
    gemm_enc_k<<<dim3(ATTN_ / 256, (SS * BB) / 128), 512, ESMEM_BYTES>>>(
        enc_out, (const __half*)p_wench, (const float*)p_decp, v_attn);

    // 4) softmax + context (s-split x8, col-half x2)
    smctx_k<<<dim3(16, BB), 128>>>(mask, enc_out, aw_dst);

    // 5) gates = [emb|ctx]@W_ih^T + hidden@W_hh^T (split-K x8, 2-product)
    gemm_k<0,1,2><<<dim3(G4 / 128, 1, 8), 256, SMEM_BYTES>>>(
        (const float*)p_xbuf, XKC, W_ih, EMB_ + ENC2_, EMB_ + ENC2_, W_hh, DECH_,
        (float*)p_gates, G4, XKC / 8, nullptr, nullptr, nullptr);

    // 6) LSTM pointwise + ctx copy
    lstm_k<<<BB, DECH_>>>(b_ih, b_hh, cell, nh_dst, nc_dst);

    // 7) output = [nh|ctx|emb] @ W_out^T + b_out (1-product, 2-deep prefetch)
    gemm_out_k<<<dim3(VOCAB_ / 128), 256, OSMEM_BYTES>>>(
        (const float*)p_obuf, W_out, out + OFF_OUT, b_out);
}